// round 1
// baseline (speedup 1.0000x reference)
#include <cuda_runtime.h>

// Attention1: b=4, n=2048, d=256, h=8, dh=32, fp32, scale = d^-0.5 = 0.0625
//
// Pipeline:
//   1) qkv_gemm_kernel : x[8192,256] @ w_qkv[256,768] + b_qkv, scattered into
//      per-head Q/K/V buffers laid out [bh][n][dh]
//   2) attention_kernel: flash-style attention per (bh, 64-row query block),
//      BN=64 key tiles, online softmax, fp32 throughout
//   3) out_gemm_kernel : att[8192,256] @ w_out[256,256] + b_out -> d_out

#define BATCH   4
#define SEQ     2048
#define DMODEL  256
#define HEADS   8
#define DH      32
#define BH      (BATCH * HEADS)     // 32
#define MROWS   (BATCH * SEQ)       // 8192

// Scratch (static device globals: allocation-free per harness rules)
__device__ float g_q[BH * SEQ * DH];      // 8 MB
__device__ float g_k[BH * SEQ * DH];      // 8 MB
__device__ float g_v[BH * SEQ * DH];      // 8 MB
__device__ float g_att[MROWS * DMODEL];   // 8 MB

// ---------------------------------------------------------------------------
// Kernel 1: QKV projection GEMM with head-layout scatter.
// Tile 64x64, BK=16, 256 threads, 4x4 register tile per thread.
// ---------------------------------------------------------------------------
__global__ void __launch_bounds__(256) qkv_gemm_kernel(
    const float* __restrict__ x,
    const float* __restrict__ w,       // [256, 768] row-major
    const float* __restrict__ bias)    // [768]
{
    __shared__ float sA[16][68];   // [kk][mm], padded
    __shared__ float sB[16][64];   // [kk][nn]

    const int t  = threadIdx.x;
    const int tx = t & 15;
    const int ty = t >> 4;
    const int n0 = blockIdx.x * 64;
    const int m0 = blockIdx.y * 64;

    // load index precompute (each thread loads 4 consecutive elements)
    const int la_m = (t * 4) >> 4;      // A: row in tile
    const int la_k = (t * 4) & 15;      // A: k offset (multiple of 4)
    const int lb_n = (t * 4) & 63;      // B: col in tile (multiple of 4)
    const int lb_k = (t * 4) >> 6;      // B: k row

    float c[4][4];
    #pragma unroll
    for (int i = 0; i < 4; i++)
        #pragma unroll
        for (int j = 0; j < 4; j++) c[i][j] = 0.f;

    for (int k0 = 0; k0 < DMODEL; k0 += 16) {
        float4 a4 = *reinterpret_cast<const float4*>(
            x + (size_t)(m0 + la_m) * DMODEL + (k0 + la_k));
        float4 b4 = *reinterpret_cast<const float4*>(
            w + (size_t)(k0 + lb_k) * (3 * DMODEL) + (n0 + lb_n));
        sA[la_k + 0][la_m] = a4.x;
        sA[la_k + 1][la_m] = a4.y;
        sA[la_k + 2][la_m] = a4.z;
        sA[la_k + 3][la_m] = a4.w;
        *reinterpret_cast<float4*>(&sB[lb_k][lb_n]) = b4;
        __syncthreads();

        #pragma unroll
        for (int kk = 0; kk < 16; kk++) {
            float av[4], bv[4];
            *reinterpret_cast<float4*>(av) = *reinterpret_cast<float4*>(&sA[kk][ty * 4]);
            *reinterpret_cast<float4*>(bv) = *reinterpret_cast<float4*>(&sB[kk][tx * 4]);
            #pragma unroll
            for (int i = 0; i < 4; i++)
                #pragma unroll
                for (int j = 0; j < 4; j++)
                    c[i][j] = fmaf(av[i], bv[j], c[i][j]);
        }
        __syncthreads();
    }

    // Epilogue: bias + scatter to head layout.
    const int jb   = n0 + tx * 4;      // global output feature (4 consecutive)
    const int part = jb >> 8;          // 0 = Q, 1 = K, 2 = V
    const int f    = jb & 255;
    const int head = f >> 5;
    const int d0   = f & 31;           // multiple of 4, within one head
    float* dst = (part == 0) ? g_q : (part == 1) ? g_k : g_v;

    float bb[4];
    *reinterpret_cast<float4*>(bb) = *reinterpret_cast<const float4*>(bias + jb);

    #pragma unroll
    for (int i = 0; i < 4; i++) {
        const int m    = m0 + ty * 4 + i;
        const int bidx = m >> 11;          // /2048
        const int irow = m & 2047;
        float4 v;
        v.x = c[i][0] + bb[0];
        v.y = c[i][1] + bb[1];
        v.z = c[i][2] + bb[2];
        v.w = c[i][3] + bb[3];
        *reinterpret_cast<float4*>(
            dst + ((size_t)(bidx * HEADS + head) * SEQ + irow) * DH + d0) = v;
    }
}

// ---------------------------------------------------------------------------
// Kernel 2: flash attention. One block = one (bh, 64 query rows).
// 256 threads. Thread (tx,ty) owns rows ty*4..+3 and (in S) keys tx*4..+3,
// (in AV) dims tx*2..+1. BN=64 key tiles, 32 tiles total.
// ---------------------------------------------------------------------------
__global__ void __launch_bounds__(256) attention_kernel()
{
    __shared__ float sQt[DH][68];    // [d][row], pre-scaled
    __shared__ float sKt[DH][68];    // [d][key]
    __shared__ float sV[64][36];     // [key][d]
    __shared__ float sP[64][68];     // [row][key]

    const int t  = threadIdx.x;
    const int tx = t & 15;
    const int ty = t >> 4;
    const int bh = blockIdx.y;
    const int r0 = blockIdx.x * 64;
    const float scale = 0.0625f;     // 256^-0.5 exactly
    const size_t base = (size_t)bh * SEQ * DH;

    // Load Q block, transposed + pre-scaled (once).
    #pragma unroll
    for (int fidx = t; fidx < 512; fidx += 256) {
        const int r  = fidx >> 3;
        const int dg = (fidx & 7) << 2;
        float4 q4 = *reinterpret_cast<const float4*>(
            g_q + base + (size_t)(r0 + r) * DH + dg);
        sQt[dg + 0][r] = q4.x * scale;
        sQt[dg + 1][r] = q4.y * scale;
        sQt[dg + 2][r] = q4.z * scale;
        sQt[dg + 3][r] = q4.w * scale;
    }

    float mrow[4], lrow[4], o[4][2];
    #pragma unroll
    for (int i = 0; i < 4; i++) {
        mrow[i] = -1e30f; lrow[i] = 0.f; o[i][0] = 0.f; o[i][1] = 0.f;
    }

    __syncthreads();

    for (int jt = 0; jt < SEQ; jt += 64) {
        // Load K tile (transposed) and V tile.
        #pragma unroll
        for (int fidx = t; fidx < 512; fidx += 256) {
            const int j  = fidx >> 3;
            const int dg = (fidx & 7) << 2;
            float4 k4 = *reinterpret_cast<const float4*>(
                g_k + base + (size_t)(jt + j) * DH + dg);
            sKt[dg + 0][j] = k4.x;
            sKt[dg + 1][j] = k4.y;
            sKt[dg + 2][j] = k4.z;
            sKt[dg + 3][j] = k4.w;
            float4 v4 = *reinterpret_cast<const float4*>(
                g_v + base + (size_t)(jt + j) * DH + dg);
            *reinterpret_cast<float4*>(&sV[j][dg]) = v4;
        }
        __syncthreads();

        // S = (Q*scale) @ K^T : 4 rows x 4 keys per thread, outer product over d.
        float s[4][4];
        #pragma unroll
        for (int i = 0; i < 4; i++)
            #pragma unroll
            for (int j = 0; j < 4; j++) s[i][j] = 0.f;

        #pragma unroll
        for (int d = 0; d < DH; d++) {
            float qv[4], kv[4];
            *reinterpret_cast<float4*>(qv) = *reinterpret_cast<float4*>(&sQt[d][ty * 4]);
            *reinterpret_cast<float4*>(kv) = *reinterpret_cast<float4*>(&sKt[d][tx * 4]);
            #pragma unroll
            for (int i = 0; i < 4; i++)
                #pragma unroll
                for (int j = 0; j < 4; j++)
                    s[i][j] = fmaf(qv[i], kv[j], s[i][j]);
        }

        // Online softmax per row (row spread across 16 tx lanes).
        #pragma unroll
        for (int rr = 0; rr < 4; rr++) {
            float lm = fmaxf(fmaxf(s[rr][0], s[rr][1]), fmaxf(s[rr][2], s[rr][3]));
            #pragma unroll
            for (int off = 1; off < 16; off <<= 1)
                lm = fmaxf(lm, __shfl_xor_sync(0xffffffffu, lm, off));
            const float nm = fmaxf(mrow[rr], lm);
            const float al = __expf(mrow[rr] - nm);
            mrow[rr] = nm;
            float p[4];
            p[0] = __expf(s[rr][0] - nm);
            p[1] = __expf(s[rr][1] - nm);
            p[2] = __expf(s[rr][2] - nm);
            p[3] = __expf(s[rr][3] - nm);
            lrow[rr] = lrow[rr] * al + (p[0] + p[1] + p[2] + p[3]);
            o[rr][0] *= al;
            o[rr][1] *= al;
            *reinterpret_cast<float4*>(&sP[ty * 4 + rr][tx * 4]) =
                *reinterpret_cast<float4*>(p);
        }
        __syncthreads();

        // O += P @ V : thread owns 4 rows x 2 dims, loops over all 64 keys.
        #pragma unroll
        for (int j0 = 0; j0 < 64; j0 += 4) {
            float p0[4], p1[4], p2[4], p3[4];
            *reinterpret_cast<float4*>(p0) = *reinterpret_cast<float4*>(&sP[ty * 4 + 0][j0]);
            *reinterpret_cast<float4*>(p1) = *reinterpret_cast<float4*>(&sP[ty * 4 + 1][j0]);
            *reinterpret_cast<float4*>(p2) = *reinterpret_cast<float4*>(&sP[ty * 4 + 2][j0]);
            *reinterpret_cast<float4*>(p3) = *reinterpret_cast<float4*>(&sP[ty * 4 + 3][j0]);
            #pragma unroll
            for (int jj = 0; jj < 4; jj++) {
                float2 v2 = *reinterpret_cast<float2*>(&sV[j0 + jj][tx * 2]);
                o[0][0] = fmaf(p0[jj], v2.x, o[0][0]);
                o[0][1] = fmaf(p0[jj], v2.y, o[0][1]);
                o[1][0] = fmaf(p1[jj], v2.x, o[1][0]);
                o[1][1] = fmaf(p1[jj], v2.y, o[1][1]);
                o[2][0] = fmaf(p2[jj], v2.x, o[2][0]);
                o[2][1] = fmaf(p2[jj], v2.y, o[2][1]);
                o[3][0] = fmaf(p3[jj], v2.x, o[3][0]);
                o[3][1] = fmaf(p3[jj], v2.y, o[3][1]);
            }
        }
        __syncthreads();
    }

    // Epilogue: normalize and store to [b, n, d] layout.
    const int b = bh >> 3;
    const int h = bh & 7;
    #pragma unroll
    for (int rr = 0; rr < 4; rr++) {
        float tot = lrow[rr];
        #pragma unroll
        for (int off = 1; off < 16; off <<= 1)
            tot += __shfl_xor_sync(0xffffffffu, tot, off);
        const float inv = 1.f / tot;
        const int row = r0 + ty * 4 + rr;
        float2 res;
        res.x = o[rr][0] * inv;
        res.y = o[rr][1] * inv;
        *reinterpret_cast<float2*>(
            g_att + ((size_t)b * SEQ + row) * DMODEL + h * DH + tx * 2) = res;
    }
}

// ---------------------------------------------------------------------------
// Kernel 3: output projection GEMM (att @ w_out + b_out).
// Same 64x64 tiled structure as kernel 1; plain row-major store.
// ---------------------------------------------------------------------------
__global__ void __launch_bounds__(256) out_gemm_kernel(
    const float* __restrict__ w,       // [256, 256]
    const float* __restrict__ bias,    // [256]
    float* __restrict__ out)           // [8192, 256]
{
    __shared__ float sA[16][68];
    __shared__ float sB[16][64];

    const int t  = threadIdx.x;
    const int tx = t & 15;
    const int ty = t >> 4;
    const int n0 = blockIdx.x * 64;
    const int m0 = blockIdx.y * 64;

    const int la_m = (t * 4) >> 4;
    const int la_k = (t * 4) & 15;
    const int lb_n = (t * 4) & 63;
    const int lb_k = (t * 4) >> 6;

    float c[4][4];
    #pragma unroll
    for (int i = 0; i < 4; i++)
        #pragma unroll
        for (int j = 0; j < 4; j++) c[i][j] = 0.f;

    for (int k0 = 0; k0 < DMODEL; k0 += 16) {
        float4 a4 = *reinterpret_cast<const float4*>(
            g_att + (size_t)(m0 + la_m) * DMODEL + (k0 + la_k));
        float4 b4 = *reinterpret_cast<const float4*>(
            w + (size_t)(k0 + lb_k) * DMODEL + (n0 + lb_n));
        sA[la_k + 0][la_m] = a4.x;
        sA[la_k + 1][la_m] = a4.y;
        sA[la_k + 2][la_m] = a4.z;
        sA[la_k + 3][la_m] = a4.w;
        *reinterpret_cast<float4*>(&sB[lb_k][lb_n]) = b4;
        __syncthreads();

        #pragma unroll
        for (int kk = 0; kk < 16; kk++) {
            float av[4], bv[4];
            *reinterpret_cast<float4*>(av) = *reinterpret_cast<float4*>(&sA[kk][ty * 4]);
            *reinterpret_cast<float4*>(bv) = *reinterpret_cast<float4*>(&sB[kk][tx * 4]);
            #pragma unroll
            for (int i = 0; i < 4; i++)
                #pragma unroll
                for (int j = 0; j < 4; j++)
                    c[i][j] = fmaf(av[i], bv[j], c[i][j]);
        }
        __syncthreads();
    }

    float bb[4];
    *reinterpret_cast<float4*>(bb) = *reinterpret_cast<const float4*>(bias + n0 + tx * 4);

    #pragma unroll
    for (int i = 0; i < 4; i++) {
        const int m = m0 + ty * 4 + i;
        float4 v;
        v.x = c[i][0] + bb[0];
        v.y = c[i][1] + bb[1];
        v.z = c[i][2] + bb[2];
        v.w = c[i][3] + bb[3];
        *reinterpret_cast<float4*>(out + (size_t)m * DMODEL + n0 + tx * 4) = v;
    }
}

// ---------------------------------------------------------------------------
extern "C" void kernel_launch(void* const* d_in, const int* in_sizes, int n_in,
                              void* d_out, int out_size)
{
    (void)in_sizes; (void)n_in; (void)out_size;
    const float* x     = (const float*)d_in[0];
    const float* w_qkv = (const float*)d_in[1];
    const float* b_qkv = (const float*)d_in[2];
    const float* w_out = (const float*)d_in[3];
    const float* b_out = (const float*)d_in[4];
    float* out = (float*)d_out;

    qkv_gemm_kernel<<<dim3(3 * DMODEL / 64, MROWS / 64), 256>>>(x, w_qkv, b_qkv);
    attention_kernel<<<dim3(SEQ / 64, BH), 256>>>();
    out_gemm_kernel<<<dim3(DMODEL / 64, MROWS / 64), 256>>>(w_out, b_out, out);
}

// round 2
// speedup vs baseline: 2.5064x; 2.5064x over previous
#include <cuda_runtime.h>
#include <cstdint>

// Attention1: b=4, n=2048, d=256, h=8, dh=32, fp32, scale = d^-0.5 = 0.0625
//
//   1) qkv_gemm_kernel : SIMT fp32 GEMM, scatters Q/K/V into [bh][n][dh];
//      K and V are tf32-rounded at store time (free pre-rounding for mma).
//   2) attention_kernel: flash attention on tensor cores, tf32 mma.sync
//      m16n8k8, fp32 softmax in registers, P kept in registers via a
//      k-permutation absorbed into the V fragment indexing.
//   3) out_gemm_kernel : SIMT fp32 GEMM.

#define BATCH   4
#define SEQ     2048
#define DMODEL  256
#define HEADS   8
#define DH      32
#define BH      (BATCH * HEADS)     // 32
#define MROWS   (BATCH * SEQ)       // 8192

__device__ float g_q[BH * SEQ * DH];      // 8 MB (raw fp32)
__device__ float g_k[BH * SEQ * DH];      // 8 MB (tf32-rounded)
__device__ float g_v[BH * SEQ * DH];      // 8 MB (tf32-rounded)
__device__ float g_att[MROWS * DMODEL];   // 8 MB

// ---- helpers ---------------------------------------------------------------
__device__ __forceinline__ uint32_t f2tf32(float x) {
    uint32_t r;
    asm("cvt.rna.tf32.f32 %0, %1;" : "=r"(r) : "f"(x));
    return r;
}
__device__ __forceinline__ float round_tf32(float x) {
    return __uint_as_float(f2tf32(x));
}
__device__ __forceinline__ void mma_tf32(float c[4],
                                         uint32_t a0, uint32_t a1, uint32_t a2, uint32_t a3,
                                         uint32_t b0, uint32_t b1) {
    asm volatile(
        "mma.sync.aligned.m16n8k8.row.col.f32.tf32.tf32.f32 "
        "{%0,%1,%2,%3}, {%4,%5,%6,%7}, {%8,%9}, {%0,%1,%2,%3};"
        : "+f"(c[0]), "+f"(c[1]), "+f"(c[2]), "+f"(c[3])
        : "r"(a0), "r"(a1), "r"(a2), "r"(a3), "r"(b0), "r"(b1));
}

// ---------------------------------------------------------------------------
// Kernel 1: QKV projection GEMM with head-layout scatter (fp32 SIMT).
// ---------------------------------------------------------------------------
__global__ void __launch_bounds__(256) qkv_gemm_kernel(
    const float* __restrict__ x,
    const float* __restrict__ w,       // [256, 768] row-major
    const float* __restrict__ bias)    // [768]
{
    __shared__ float sA[16][68];
    __shared__ float sB[16][64];

    const int t  = threadIdx.x;
    const int tx = t & 15;
    const int ty = t >> 4;
    const int n0 = blockIdx.x * 64;
    const int m0 = blockIdx.y * 64;

    const int la_m = (t * 4) >> 4;
    const int la_k = (t * 4) & 15;
    const int lb_n = (t * 4) & 63;
    const int lb_k = (t * 4) >> 6;

    float c[4][4];
    #pragma unroll
    for (int i = 0; i < 4; i++)
        #pragma unroll
        for (int j = 0; j < 4; j++) c[i][j] = 0.f;

    for (int k0 = 0; k0 < DMODEL; k0 += 16) {
        float4 a4 = *reinterpret_cast<const float4*>(
            x + (size_t)(m0 + la_m) * DMODEL + (k0 + la_k));
        float4 b4 = *reinterpret_cast<const float4*>(
            w + (size_t)(k0 + lb_k) * (3 * DMODEL) + (n0 + lb_n));
        sA[la_k + 0][la_m] = a4.x;
        sA[la_k + 1][la_m] = a4.y;
        sA[la_k + 2][la_m] = a4.z;
        sA[la_k + 3][la_m] = a4.w;
        *reinterpret_cast<float4*>(&sB[lb_k][lb_n]) = b4;
        __syncthreads();

        #pragma unroll
        for (int kk = 0; kk < 16; kk++) {
            float av[4], bv[4];
            *reinterpret_cast<float4*>(av) = *reinterpret_cast<float4*>(&sA[kk][ty * 4]);
            *reinterpret_cast<float4*>(bv) = *reinterpret_cast<float4*>(&sB[kk][tx * 4]);
            #pragma unroll
            for (int i = 0; i < 4; i++)
                #pragma unroll
                for (int j = 0; j < 4; j++)
                    c[i][j] = fmaf(av[i], bv[j], c[i][j]);
        }
        __syncthreads();
    }

    const int jb   = n0 + tx * 4;
    const int part = jb >> 8;          // 0 = Q, 1 = K, 2 = V
    const int f    = jb & 255;
    const int head = f >> 5;
    const int d0   = f & 31;
    float* dst = (part == 0) ? g_q : (part == 1) ? g_k : g_v;

    float bb[4];
    *reinterpret_cast<float4*>(bb) = *reinterpret_cast<const float4*>(bias + jb);

    #pragma unroll
    for (int i = 0; i < 4; i++) {
        const int m    = m0 + ty * 4 + i;
        const int bidx = m >> 11;
        const int irow = m & 2047;
        float4 v;
        v.x = c[i][0] + bb[0];
        v.y = c[i][1] + bb[1];
        v.z = c[i][2] + bb[2];
        v.w = c[i][3] + bb[3];
        if (part != 0) {   // pre-round K/V to tf32 once, here (free per-tile later)
            v.x = round_tf32(v.x);
            v.y = round_tf32(v.y);
            v.z = round_tf32(v.z);
            v.w = round_tf32(v.w);
        }
        *reinterpret_cast<float4*>(
            dst + ((size_t)(bidx * HEADS + head) * SEQ + irow) * DH + d0) = v;
    }
}

// ---------------------------------------------------------------------------
// Kernel 2: flash attention on tensor cores (tf32 mma.sync m16n8k8).
// Block = 128 threads (4 warps). BM = 64 query rows (16/warp), BN = 64 keys.
// ---------------------------------------------------------------------------
__global__ void __launch_bounds__(128) attention_kernel()
{
    __shared__ float sK[64][36];   // [key][d], stride 36 -> conflict-free frags
    __shared__ float sV[64][36];

    const int t   = threadIdx.x;
    const int w   = t >> 5;        // warp 0..3
    const int lan = t & 31;
    const int g   = lan >> 2;      // group 0..7
    const int tig = lan & 3;       // thread in group
    const int bh  = blockIdx.y;
    const int r0  = blockIdx.x * 64;
    const size_t base = (size_t)bh * SEQ * DH;

    // scale folds softmax's base-e into exp2: S' = (QK^T)*d^-0.5*log2(e)
    const float scale = 0.0625f * 1.4426950408889634f;

    // Q A-fragments (16 regs), loaded once, scaled + tf32-rounded.
    const int qr0 = r0 + w * 16 + g;       // row for a0/a2
    uint32_t qa[4][4];
    #pragma unroll
    for (int ks = 0; ks < 4; ks++) {
        const int kb = ks * 8;
        qa[ks][0] = f2tf32(g_q[base + (size_t)qr0       * DH + kb + tig    ] * scale);
        qa[ks][1] = f2tf32(g_q[base + (size_t)(qr0 + 8) * DH + kb + tig    ] * scale);
        qa[ks][2] = f2tf32(g_q[base + (size_t)qr0       * DH + kb + tig + 4] * scale);
        qa[ks][3] = f2tf32(g_q[base + (size_t)(qr0 + 8) * DH + kb + tig + 4] * scale);
    }

    // Online softmax state: rows g (idx 0) and g+8 (idx 1) of this warp tile.
    float m0 = -1e30f, m1 = -1e30f;     // running max (log2 domain)
    float l0 = 0.f, l1 = 0.f;           // thread-partial row sums
    float o[4][4];                      // O frags: 4 d-chunks x (c0..c3)
    #pragma unroll
    for (int i = 0; i < 4; i++)
        #pragma unroll
        for (int j = 0; j < 4; j++) o[i][j] = 0.f;

    for (int jt = 0; jt < SEQ; jt += 64) {
        // ---- load K/V tile (tf32-prerounded in gmem) -----------------------
        #pragma unroll
        for (int it = 0; it < 4; it++) {
            const int i  = t + it * 128;      // 0..511 float4 slots
            const int j  = i >> 3;
            const int dg = (i & 7) << 2;
            *reinterpret_cast<float4*>(&sK[j][dg]) =
                *reinterpret_cast<const float4*>(g_k + base + (size_t)(jt + j) * DH + dg);
            *reinterpret_cast<float4*>(&sV[j][dg]) =
                *reinterpret_cast<const float4*>(g_v + base + (size_t)(jt + j) * DH + dg);
        }
        __syncthreads();

        // ---- S = Q' @ K^T : 8 n-frags of 16x8, k = 32 (4 slices) -----------
        float sc[8][4];
        #pragma unroll
        for (int nf = 0; nf < 8; nf++) {
            sc[nf][0] = sc[nf][1] = sc[nf][2] = sc[nf][3] = 0.f;
            const int key = nf * 8 + g;     // B col for this thread
            #pragma unroll
            for (int ks = 0; ks < 4; ks++) {
                const int kb = ks * 8;
                uint32_t b0 = __float_as_uint(sK[key][kb + tig]);
                uint32_t b1 = __float_as_uint(sK[key][kb + tig + 4]);
                mma_tf32(sc[nf], qa[ks][0], qa[ks][1], qa[ks][2], qa[ks][3], b0, b1);
            }
        }

        // ---- online softmax (fp32, exp2) -----------------------------------
        float mx0 = -1e30f, mx1 = -1e30f;
        #pragma unroll
        for (int nf = 0; nf < 8; nf++) {
            mx0 = fmaxf(mx0, fmaxf(sc[nf][0], sc[nf][1]));
            mx1 = fmaxf(mx1, fmaxf(sc[nf][2], sc[nf][3]));
        }
        mx0 = fmaxf(mx0, __shfl_xor_sync(0xffffffffu, mx0, 1));
        mx0 = fmaxf(mx0, __shfl_xor_sync(0xffffffffu, mx0, 2));
        mx1 = fmaxf(mx1, __shfl_xor_sync(0xffffffffu, mx1, 1));
        mx1 = fmaxf(mx1, __shfl_xor_sync(0xffffffffu, mx1, 2));

        const float nm0 = fmaxf(m0, mx0);
        const float nm1 = fmaxf(m1, mx1);
        const float al0 = exp2f(m0 - nm0);
        const float al1 = exp2f(m1 - nm1);
        m0 = nm0; m1 = nm1;

        uint32_t pu[8][4];
        float sum0 = 0.f, sum1 = 0.f;
        #pragma unroll
        for (int nf = 0; nf < 8; nf++) {
            float p0 = exp2f(sc[nf][0] - nm0);
            float p1 = exp2f(sc[nf][1] - nm0);
            float p2 = exp2f(sc[nf][2] - nm1);
            float p3 = exp2f(sc[nf][3] - nm1);
            sum0 += p0 + p1;
            sum1 += p2 + p3;
            pu[nf][0] = f2tf32(p0);
            pu[nf][1] = f2tf32(p1);
            pu[nf][2] = f2tf32(p2);
            pu[nf][3] = f2tf32(p3);
        }
        l0 = l0 * al0 + sum0;
        l1 = l1 * al1 + sum1;
        #pragma unroll
        for (int nf2 = 0; nf2 < 4; nf2++) {
            o[nf2][0] *= al0; o[nf2][1] *= al0;
            o[nf2][2] *= al1; o[nf2][3] *= al1;
        }

        // ---- O += P @ V ----------------------------------------------------
        // P stays in C-fragment layout; the intra-slice column permutation
        // sigma(s) = (s<4 ? 2s : 2(s-4)+1) is applied to V's key rows instead.
        #pragma unroll
        for (int ks2 = 0; ks2 < 8; ks2++) {
            const int kr0 = ks2 * 8 + 2 * tig;       // sigma(tig)
            const int kr1 = kr0 + 1;                 // sigma(tig+4)
            #pragma unroll
            for (int nf2 = 0; nf2 < 4; nf2++) {
                const int dcol = nf2 * 8 + g;
                uint32_t b0 = __float_as_uint(sV[kr0][dcol]);
                uint32_t b1 = __float_as_uint(sV[kr1][dcol]);
                mma_tf32(o[nf2], pu[ks2][0], pu[ks2][2], pu[ks2][1], pu[ks2][3], b0, b1);
            }
        }
        __syncthreads();
    }

    // ---- epilogue: reduce l across quad, normalize, store ------------------
    l0 += __shfl_xor_sync(0xffffffffu, l0, 1);
    l0 += __shfl_xor_sync(0xffffffffu, l0, 2);
    l1 += __shfl_xor_sync(0xffffffffu, l1, 1);
    l1 += __shfl_xor_sync(0xffffffffu, l1, 2);
    const float inv0 = 1.f / l0;
    const float inv1 = 1.f / l1;

    const int b = bh >> 3;
    const int h = bh & 7;
    const int row0 = r0 + w * 16 + g;
    #pragma unroll
    for (int nf2 = 0; nf2 < 4; nf2++) {
        const int dcol = h * DH + nf2 * 8 + 2 * tig;
        float2 v0, v1;
        v0.x = o[nf2][0] * inv0; v0.y = o[nf2][1] * inv0;
        v1.x = o[nf2][2] * inv1; v1.y = o[nf2][3] * inv1;
        *reinterpret_cast<float2*>(
            g_att + ((size_t)b * SEQ + row0) * DMODEL + dcol) = v0;
        *reinterpret_cast<float2*>(
            g_att + ((size_t)b * SEQ + row0 + 8) * DMODEL + dcol) = v1;
    }
}

// ---------------------------------------------------------------------------
// Kernel 3: output projection GEMM (fp32 SIMT).
// ---------------------------------------------------------------------------
__global__ void __launch_bounds__(256) out_gemm_kernel(
    const float* __restrict__ w,       // [256, 256]
    const float* __restrict__ bias,    // [256]
    float* __restrict__ out)           // [8192, 256]
{
    __shared__ float sA[16][68];
    __shared__ float sB[16][64];

    const int t  = threadIdx.x;
    const int tx = t & 15;
    const int ty = t >> 4;
    const int n0 = blockIdx.x * 64;
    const int m0 = blockIdx.y * 64;

    const int la_m = (t * 4) >> 4;
    const int la_k = (t * 4) & 15;
    const int lb_n = (t * 4) & 63;
    const int lb_k = (t * 4) >> 6;

    float c[4][4];
    #pragma unroll
    for (int i = 0; i < 4; i++)
        #pragma unroll
        for (int j = 0; j < 4; j++) c[i][j] = 0.f;

    for (int k0 = 0; k0 < DMODEL; k0 += 16) {
        float4 a4 = *reinterpret_cast<const float4*>(
            g_att + (size_t)(m0 + la_m) * DMODEL + (k0 + la_k));
        float4 b4 = *reinterpret_cast<const float4*>(
            w + (size_t)(k0 + lb_k) * DMODEL + (n0 + lb_n));
        sA[la_k + 0][la_m] = a4.x;
        sA[la_k + 1][la_m] = a4.y;
        sA[la_k + 2][la_m] = a4.z;
        sA[la_k + 3][la_m] = a4.w;
        *reinterpret_cast<float4*>(&sB[lb_k][lb_n]) = b4;
        __syncthreads();

        #pragma unroll
        for (int kk = 0; kk < 16; kk++) {
            float av[4], bv[4];
            *reinterpret_cast<float4*>(av) = *reinterpret_cast<float4*>(&sA[kk][ty * 4]);
            *reinterpret_cast<float4*>(bv) = *reinterpret_cast<float4*>(&sB[kk][tx * 4]);
            #pragma unroll
            for (int i = 0; i < 4; i++)
                #pragma unroll
                for (int j = 0; j < 4; j++)
                    c[i][j] = fmaf(av[i], bv[j], c[i][j]);
        }
        __syncthreads();
    }

    float bb[4];
    *reinterpret_cast<float4*>(bb) = *reinterpret_cast<const float4*>(bias + n0 + tx * 4);

    #pragma unroll
    for (int i = 0; i < 4; i++) {
        const int m = m0 + ty * 4 + i;
        float4 v;
        v.x = c[i][0] + bb[0];
        v.y = c[i][1] + bb[1];
        v.z = c[i][2] + bb[2];
        v.w = c[i][3] + bb[3];
        *reinterpret_cast<float4*>(out + (size_t)m * DMODEL + n0 + tx * 4) = v;
    }
}

// ---------------------------------------------------------------------------
extern "C" void kernel_launch(void* const* d_in, const int* in_sizes, int n_in,
                              void* d_out, int out_size)
{
    (void)in_sizes; (void)n_in; (void)out_size;
    const float* x     = (const float*)d_in[0];
    const float* w_qkv = (const float*)d_in[1];
    const float* b_qkv = (const float*)d_in[2];
    const float* w_out = (const float*)d_in[3];
    const float* b_out = (const float*)d_in[4];
    float* out = (float*)d_out;

    qkv_gemm_kernel<<<dim3(3 * DMODEL / 64, MROWS / 64), 256>>>(x, w_qkv, b_qkv);
    attention_kernel<<<dim3(SEQ / 64, BH), 128>>>();
    out_gemm_kernel<<<dim3(DMODEL / 64, MROWS / 64), 256>>>(w_out, b_out, out);
}

// round 3
// speedup vs baseline: 3.3269x; 1.3274x over previous
#include <cuda_runtime.h>
#include <cstdint>

// Attention1: b=4, n=2048, d=256, h=8, dh=32, fp32, scale = d^-0.5 = 0.0625
//
//   1) qkv_gemm_kernel : tf32 mma.sync GEMM, scatters Q/K/V into [bh][n][dh];
//      K and V tf32-rounded at store time.
//   2) attention_kernel: flash attention on tensor cores (tf32 mma.sync),
//      P kept in registers via k-permutation absorbed into V indexing.
//   3) out_gemm_kernel : tf32 mma.sync GEMM.

#define BATCH   4
#define SEQ     2048
#define DMODEL  256
#define HEADS   8
#define DH      32
#define BH      (BATCH * HEADS)     // 32
#define MROWS   (BATCH * SEQ)       // 8192

__device__ float g_q[BH * SEQ * DH];      // 8 MB
__device__ float g_k[BH * SEQ * DH];      // 8 MB (tf32-rounded)
__device__ float g_v[BH * SEQ * DH];      // 8 MB (tf32-rounded)
__device__ float g_att[MROWS * DMODEL];   // 8 MB

// ---- helpers ---------------------------------------------------------------
__device__ __forceinline__ uint32_t f2tf32(float x) {
    uint32_t r;
    asm("cvt.rna.tf32.f32 %0, %1;" : "=r"(r) : "f"(x));
    return r;
}
__device__ __forceinline__ float round_tf32(float x) {
    return __uint_as_float(f2tf32(x));
}
__device__ __forceinline__ void mma_tf32(float c[4],
                                         uint32_t a0, uint32_t a1, uint32_t a2, uint32_t a3,
                                         uint32_t b0, uint32_t b1) {
    asm volatile(
        "mma.sync.aligned.m16n8k8.row.col.f32.tf32.tf32.f32 "
        "{%0,%1,%2,%3}, {%4,%5,%6,%7}, {%8,%9}, {%0,%1,%2,%3};"
        : "+f"(c[0]), "+f"(c[1]), "+f"(c[2]), "+f"(c[3])
        : "r"(a0), "r"(a1), "r"(a2), "r"(a3), "r"(b0), "r"(b1));
}

// ---------------------------------------------------------------------------
// Shared GEMM core: C[128x64] += A[128x256] * B[256x64] (B given as w[k][n]).
// 256 threads / 8 warps; warp (wm,wn) owns a 32x32 subtile.
// sA[128][36] and sBt[64][36] hold tf32-converted tiles; frag reads are
// conflict-free (bank = 4g + tig).
// ---------------------------------------------------------------------------
struct GemmAcc { float c[2][4][4]; };   // [mf][nf][reg]

template<int LDB>   // row stride (elements) of the B matrix in gmem
__device__ __forceinline__ void gemm_128x64_tf32(
    const float* __restrict__ Abase,    // A[m0..m0+127][0..255], row stride 256
    const float* __restrict__ Bbase,    // w[0..255][n0..n0+63], row stride LDB
    float sA[128][36], float sBt[64][36], GemmAcc& acc)
{
    const int t   = threadIdx.x;
    const int w   = t >> 5;
    const int lan = t & 31;
    const int g   = lan >> 2;
    const int tig = lan & 3;
    const int wm  = w & 3;
    const int wn  = w >> 2;

    #pragma unroll
    for (int mf = 0; mf < 2; mf++)
        #pragma unroll
        for (int nf = 0; nf < 4; nf++)
            #pragma unroll
            for (int r = 0; r < 4; r++) acc.c[mf][nf][r] = 0.f;

    for (int k0 = 0; k0 < DMODEL; k0 += 32) {
        // stage A tile (128x32), tf32-converted
        #pragma unroll
        for (int it = 0; it < 4; it++) {
            const int i4  = t + it * 256;          // 1024 float4 slots
            const int row = i4 >> 3;
            const int c4  = (i4 & 7) << 2;
            float4 a4 = *reinterpret_cast<const float4*>(
                Abase + (size_t)row * DMODEL + k0 + c4);
            float4 s;
            s.x = round_tf32(a4.x); s.y = round_tf32(a4.y);
            s.z = round_tf32(a4.z); s.w = round_tf32(a4.w);
            *reinterpret_cast<float4*>(&sA[row][c4]) = s;
        }
        // stage B tile (32x64) transposed -> sBt[n][k], tf32-converted
        #pragma unroll
        for (int it = 0; it < 2; it++) {
            const int i4  = t + it * 256;          // 512 float4 slots
            const int kk  = i4 >> 4;
            const int nn4 = (i4 & 15) << 2;
            float4 b4 = *reinterpret_cast<const float4*>(
                Bbase + (size_t)(k0 + kk) * LDB + nn4);
            sBt[nn4 + 0][kk] = round_tf32(b4.x);
            sBt[nn4 + 1][kk] = round_tf32(b4.y);
            sBt[nn4 + 2][kk] = round_tf32(b4.z);
            sBt[nn4 + 3][kk] = round_tf32(b4.w);
        }
        __syncthreads();

        #pragma unroll
        for (int ks = 0; ks < 4; ks++) {
            const int kb = ks * 8;
            uint32_t af[2][4];
            #pragma unroll
            for (int mf = 0; mf < 2; mf++) {
                const int r0 = wm * 32 + mf * 16 + g;
                af[mf][0] = __float_as_uint(sA[r0    ][kb + tig]);
                af[mf][1] = __float_as_uint(sA[r0 + 8][kb + tig]);
                af[mf][2] = __float_as_uint(sA[r0    ][kb + tig + 4]);
                af[mf][3] = __float_as_uint(sA[r0 + 8][kb + tig + 4]);
            }
            #pragma unroll
            for (int nf = 0; nf < 4; nf++) {
                const int n = wn * 32 + nf * 8 + g;
                const uint32_t b0 = __float_as_uint(sBt[n][kb + tig]);
                const uint32_t b1 = __float_as_uint(sBt[n][kb + tig + 4]);
                #pragma unroll
                for (int mf = 0; mf < 2; mf++)
                    mma_tf32(acc.c[mf][nf], af[mf][0], af[mf][1], af[mf][2], af[mf][3], b0, b1);
            }
        }
        __syncthreads();
    }
}

// ---------------------------------------------------------------------------
// Kernel 1: QKV projection (tf32 mma) with head-layout scatter.
// ---------------------------------------------------------------------------
__global__ void __launch_bounds__(256) qkv_gemm_kernel(
    const float* __restrict__ x,
    const float* __restrict__ wq,      // [256, 768]
    const float* __restrict__ bias)    // [768]
{
    __shared__ float sA[128][36];
    __shared__ float sBt[64][36];

    const int n0 = blockIdx.x * 64;
    const int m0 = blockIdx.y * 128;

    GemmAcc acc;
    gemm_128x64_tf32<3 * DMODEL>(x + (size_t)m0 * DMODEL, wq + n0, sA, sBt, acc);

    const int t   = threadIdx.x;
    const int w   = t >> 5;
    const int lan = t & 31;
    const int g   = lan >> 2;
    const int tig = lan & 3;
    const int wm  = w & 3;
    const int wn  = w >> 2;

    #pragma unroll
    for (int nf = 0; nf < 4; nf++) {
        const int jb   = n0 + wn * 32 + nf * 8 + 2 * tig;  // even column pair
        const int part = jb >> 8;          // 0=Q 1=K 2=V
        const int f    = jb & 255;
        const int head = f >> 5;
        const int d0   = f & 31;
        float* dst = (part == 0) ? g_q : (part == 1) ? g_k : g_v;
        const float b0 = bias[jb], b1 = bias[jb + 1];

        #pragma unroll
        for (int mf = 0; mf < 2; mf++) {
            #pragma unroll
            for (int half = 0; half < 2; half++) {
                const int m    = m0 + wm * 32 + mf * 16 + g + half * 8;
                const int bidx = m >> 11;
                const int irow = m & 2047;
                float2 v;
                v.x = acc.c[mf][nf][half * 2 + 0] + b0;
                v.y = acc.c[mf][nf][half * 2 + 1] + b1;
                if (part != 0) { v.x = round_tf32(v.x); v.y = round_tf32(v.y); }
                *reinterpret_cast<float2*>(
                    dst + ((size_t)(bidx * HEADS + head) * SEQ + irow) * DH + d0) = v;
            }
        }
    }
}

// ---------------------------------------------------------------------------
// Kernel 2: flash attention on tensor cores (unchanged from R2).
// ---------------------------------------------------------------------------
__global__ void __launch_bounds__(128) attention_kernel()
{
    __shared__ float sK[64][36];
    __shared__ float sV[64][36];

    const int t   = threadIdx.x;
    const int w   = t >> 5;
    const int lan = t & 31;
    const int g   = lan >> 2;
    const int tig = lan & 3;
    const int bh  = blockIdx.y;
    const int r0  = blockIdx.x * 64;
    const size_t base = (size_t)bh * SEQ * DH;

    const float scale = 0.0625f * 1.4426950408889634f;

    const int qr0 = r0 + w * 16 + g;
    uint32_t qa[4][4];
    #pragma unroll
    for (int ks = 0; ks < 4; ks++) {
        const int kb = ks * 8;
        qa[ks][0] = f2tf32(g_q[base + (size_t)qr0       * DH + kb + tig    ] * scale);
        qa[ks][1] = f2tf32(g_q[base + (size_t)(qr0 + 8) * DH + kb + tig    ] * scale);
        qa[ks][2] = f2tf32(g_q[base + (size_t)qr0       * DH + kb + tig + 4] * scale);
        qa[ks][3] = f2tf32(g_q[base + (size_t)(qr0 + 8) * DH + kb + tig + 4] * scale);
    }

    float m0 = -1e30f, m1 = -1e30f;
    float l0 = 0.f, l1 = 0.f;
    float o[4][4];
    #pragma unroll
    for (int i = 0; i < 4; i++)
        #pragma unroll
        for (int j = 0; j < 4; j++) o[i][j] = 0.f;

    for (int jt = 0; jt < SEQ; jt += 64) {
        #pragma unroll
        for (int it = 0; it < 4; it++) {
            const int i  = t + it * 128;
            const int j  = i >> 3;
            const int dg = (i & 7) << 2;
            *reinterpret_cast<float4*>(&sK[j][dg]) =
                *reinterpret_cast<const float4*>(g_k + base + (size_t)(jt + j) * DH + dg);
            *reinterpret_cast<float4*>(&sV[j][dg]) =
                *reinterpret_cast<const float4*>(g_v + base + (size_t)(jt + j) * DH + dg);
        }
        __syncthreads();

        float sc[8][4];
        #pragma unroll
        for (int nf = 0; nf < 8; nf++) {
            sc[nf][0] = sc[nf][1] = sc[nf][2] = sc[nf][3] = 0.f;
            const int key = nf * 8 + g;
            #pragma unroll
            for (int ks = 0; ks < 4; ks++) {
                const int kb = ks * 8;
                uint32_t b0 = __float_as_uint(sK[key][kb + tig]);
                uint32_t b1 = __float_as_uint(sK[key][kb + tig + 4]);
                mma_tf32(sc[nf], qa[ks][0], qa[ks][1], qa[ks][2], qa[ks][3], b0, b1);
            }
        }

        float mx0 = -1e30f, mx1 = -1e30f;
        #pragma unroll
        for (int nf = 0; nf < 8; nf++) {
            mx0 = fmaxf(mx0, fmaxf(sc[nf][0], sc[nf][1]));
            mx1 = fmaxf(mx1, fmaxf(sc[nf][2], sc[nf][3]));
        }
        mx0 = fmaxf(mx0, __shfl_xor_sync(0xffffffffu, mx0, 1));
        mx0 = fmaxf(mx0, __shfl_xor_sync(0xffffffffu, mx0, 2));
        mx1 = fmaxf(mx1, __shfl_xor_sync(0xffffffffu, mx1, 1));
        mx1 = fmaxf(mx1, __shfl_xor_sync(0xffffffffu, mx1, 2));

        const float nm0 = fmaxf(m0, mx0);
        const float nm1 = fmaxf(m1, mx1);
        const float al0 = exp2f(m0 - nm0);
        const float al1 = exp2f(m1 - nm1);
        m0 = nm0; m1 = nm1;

        uint32_t pu[8][4];
        float sum0 = 0.f, sum1 = 0.f;
        #pragma unroll
        for (int nf = 0; nf < 8; nf++) {
            float p0 = exp2f(sc[nf][0] - nm0);
            float p1 = exp2f(sc[nf][1] - nm0);
            float p2 = exp2f(sc[nf][2] - nm1);
            float p3 = exp2f(sc[nf][3] - nm1);
            sum0 += p0 + p1;
            sum1 += p2 + p3;
            pu[nf][0] = f2tf32(p0);
            pu[nf][1] = f2tf32(p1);
            pu[nf][2] = f2tf32(p2);
            pu[nf][3] = f2tf32(p3);
        }
        l0 = l0 * al0 + sum0;
        l1 = l1 * al1 + sum1;
        #pragma unroll
        for (int nf2 = 0; nf2 < 4; nf2++) {
            o[nf2][0] *= al0; o[nf2][1] *= al0;
            o[nf2][2] *= al1; o[nf2][3] *= al1;
        }

        #pragma unroll
        for (int ks2 = 0; ks2 < 8; ks2++) {
            const int kr0 = ks2 * 8 + 2 * tig;
            const int kr1 = kr0 + 1;
            #pragma unroll
            for (int nf2 = 0; nf2 < 4; nf2++) {
                const int dcol = nf2 * 8 + g;
                uint32_t b0 = __float_as_uint(sV[kr0][dcol]);
                uint32_t b1 = __float_as_uint(sV[kr1][dcol]);
                mma_tf32(o[nf2], pu[ks2][0], pu[ks2][2], pu[ks2][1], pu[ks2][3], b0, b1);
            }
        }
        __syncthreads();
    }

    l0 += __shfl_xor_sync(0xffffffffu, l0, 1);
    l0 += __shfl_xor_sync(0xffffffffu, l0, 2);
    l1 += __shfl_xor_sync(0xffffffffu, l1, 1);
    l1 += __shfl_xor_sync(0xffffffffu, l1, 2);
    const float inv0 = 1.f / l0;
    const float inv1 = 1.f / l1;

    const int b = bh >> 3;
    const int h = bh & 7;
    const int row0 = r0 + w * 16 + g;
    #pragma unroll
    for (int nf2 = 0; nf2 < 4; nf2++) {
        const int dcol = h * DH + nf2 * 8 + 2 * tig;
        float2 v0, v1;
        v0.x = o[nf2][0] * inv0; v0.y = o[nf2][1] * inv0;
        v1.x = o[nf2][2] * inv1; v1.y = o[nf2][3] * inv1;
        *reinterpret_cast<float2*>(
            g_att + ((size_t)b * SEQ + row0) * DMODEL + dcol) = v0;
        *reinterpret_cast<float2*>(
            g_att + ((size_t)b * SEQ + row0 + 8) * DMODEL + dcol) = v1;
    }
}

// ---------------------------------------------------------------------------
// Kernel 3: output projection (tf32 mma).
// ---------------------------------------------------------------------------
__global__ void __launch_bounds__(256) out_gemm_kernel(
    const float* __restrict__ wo,      // [256, 256]
    const float* __restrict__ bias,    // [256]
    float* __restrict__ out)           // [8192, 256]
{
    __shared__ float sA[128][36];
    __shared__ float sBt[64][36];

    const int n0 = blockIdx.x * 64;
    const int m0 = blockIdx.y * 128;

    GemmAcc acc;
    gemm_128x64_tf32<DMODEL>(g_att + (size_t)m0 * DMODEL, wo + n0, sA, sBt, acc);

    const int t   = threadIdx.x;
    const int w   = t >> 5;
    const int lan = t & 31;
    const int g   = lan >> 2;
    const int tig = lan & 3;
    const int wm  = w & 3;
    const int wn  = w >> 2;

    #pragma unroll
    for (int nf = 0; nf < 4; nf++) {
        const int jb = n0 + wn * 32 + nf * 8 + 2 * tig;
        const float b0 = bias[jb], b1 = bias[jb + 1];
        #pragma unroll
        for (int mf = 0; mf < 2; mf++) {
            #pragma unroll
            for (int half = 0; half < 2; half++) {
                const int m = m0 + wm * 32 + mf * 16 + g + half * 8;
                float2 v;
                v.x = acc.c[mf][nf][half * 2 + 0] + b0;
                v.y = acc.c[mf][nf][half * 2 + 1] + b1;
                *reinterpret_cast<float2*>(out + (size_t)m * DMODEL + jb) = v;
            }
        }
    }
}

// ---------------------------------------------------------------------------
extern "C" void kernel_launch(void* const* d_in, const int* in_sizes, int n_in,
                              void* d_out, int out_size)
{
    (void)in_sizes; (void)n_in; (void)out_size;
    const float* x     = (const float*)d_in[0];
    const float* w_qkv = (const float*)d_in[1];
    const float* b_qkv = (const float*)d_in[2];
    const float* w_out = (const float*)d_in[3];
    const float* b_out = (const float*)d_in[4];
    float* out = (float*)d_out;

    qkv_gemm_kernel<<<dim3(3 * DMODEL / 64, MROWS / 128), 256>>>(x, w_qkv, b_qkv);
    attention_kernel<<<dim3(SEQ / 64, BH), 128>>>();
    out_gemm_kernel<<<dim3(DMODEL / 64, MROWS / 128), 256>>>(w_out, b_out, out);
}